// round 16
// baseline (speedup 1.0000x reference)
#include <cuda_runtime.h>
#include <cuda_fp16.h>
#include <cstdint>

#define H 128
#define NMAX 100000

// Scratch: per-node A = z@W1_top + b1 (cols 0..127), B = z@W1_bot (cols 128..255), fp16
__device__ __align__(16) __half g_ABh[(size_t)NMAX * 256];
// Pre-transposed, tf32-rounded Wcat^T: layout [n][k], n in [0,256), k in [0,128)
__device__ __align__(16) float g_Wt[256 * 128];

__device__ __forceinline__ float to_tf32(float x) {
    float r; asm("cvt.rna.tf32.f32 %0, %1;" : "=f"(r) : "f"(x)); return r;
}

// ---------------- prep: build W^T (tf32-rounded, transposed) ----------------
__global__ void prep_kernel(const float* __restrict__ W1) {
    int idx = blockIdx.x * blockDim.x + threadIdx.x;   // 0..32767
    int n = idx & 255;
    int k = idx >> 8;
    float v = (n < 128) ? W1[(size_t)k * 128 + n]
                        : W1[(size_t)(k + 128) * 128 + (n - 128)];
    g_Wt[(size_t)n * 128 + k] = to_tf32(v);
}

// ---------------- persistent tf32 GEMM: ldmatrix + register prefetch + staged epilogue ----------------
#define ASF 132   // fp32 words per SMEM row (132 mod 32 = 4 -> conflict-free ldmatrix)

__device__ __forceinline__ void mma_tf32(float* d, const uint32_t* a,
                                         uint32_t b0, uint32_t b1) {
    asm volatile(
        "mma.sync.aligned.m16n8k8.row.col.f32.tf32.tf32.f32 "
        "{%0,%1,%2,%3}, {%4,%5,%6,%7}, {%8,%9}, {%0,%1,%2,%3};"
        : "+f"(d[0]), "+f"(d[1]), "+f"(d[2]), "+f"(d[3])
        : "r"(a[0]), "r"(a[1]), "r"(a[2]), "r"(a[3]), "r"(b0), "r"(b1));
}

__device__ __forceinline__ uint32_t smem_u32(const void* p) {
    uint32_t a;
    asm("{ .reg .u64 t; cvta.to.shared.u64 t, %1; cvt.u32.u64 %0, t; }" : "=r"(a) : "l"(p));
    return a;
}

__device__ __forceinline__ void ldsm_x4(uint32_t* r, uint32_t saddr) {
    asm volatile("ldmatrix.sync.aligned.m8n8.x4.shared.b16 {%0,%1,%2,%3}, [%4];"
                 : "=r"(r[0]), "=r"(r[1]), "=r"(r[2]), "=r"(r[3]) : "r"(saddr));
}

__device__ __forceinline__ void cp_async16(void* smem_dst, const void* gsrc) {
    uint32_t a = smem_u32(smem_dst);
    asm volatile("cp.async.cg.shared.global [%0], [%1], 16;" :: "r"(a), "l"(gsrc) : "memory");
}

__global__ __launch_bounds__(256, 2) void node_gemm_tf32(
    const float* __restrict__ z,
    const float* __restrict__ b1,
    int n_nodes)
{
    extern __shared__ __align__(16) float smem[];
    float* As = smem;             // [64][ASF] fp32 z-tile; reused as fp16 staging [64][264]
    float* Bs = smem + 64 * ASF;  // [128 n][ASF k]
    __half* stg = (__half*)As;    // staging: 64 rows x 264 halves (132 words) = same footprint

    const int tid = threadIdx.x;
    const int wid = tid >> 5;
    const int lane = tid & 31;
    const int half = blockIdx.y;
    const int n_tiles = (n_nodes + 63) >> 6;

    // ---- async copy of pre-rounded W^T half [128 x 128] (ONCE per CTA) ----
    {
        const float* src = g_Wt + (size_t)half * 128 * 128;
        #pragma unroll
        for (int i = 0; i < 16; i++) {
            int idx = tid + i * 256;
            int r = idx >> 5;
            int q = idx & 31;
            cp_async16(Bs + r * ASF + q * 4, src + (size_t)r * 128 + q * 4);
        }
        asm volatile("cp.async.commit_group;" ::: "memory");
        asm volatile("cp.async.wait_group 0;" ::: "memory");
    }

    const int wm = wid & 1;
    const int wn = wid >> 1;
    const int gr = lane >> 2;
    const int cc = lane & 3;

    // ---- precompute ldmatrix lane addresses ----
    uint32_t aAddr[2], bAddr[2];
    {
        int lrow = (lane & 7) + 8 * ((lane >> 3) & 1);
        int lword = 4 * ((lane >> 4) & 1);
        #pragma unroll
        for (int t = 0; t < 2; t++)
            aAddr[t] = smem_u32(As + (wm * 32 + t * 16 + lrow) * ASF + lword);
        int brow = (lane & 7) + 8 * ((lane >> 4) & 1);
        int bword = 4 * ((lane >> 3) & 1);
        #pragma unroll
        for (int t = 0; t < 2; t++)
            bAddr[t] = smem_u32(Bs + (wn * 32 + t * 16 + brow) * ASF + bword);
    }

    // b1 values for this thread's columns (tile-invariant)
    float bxy[4][2];
    #pragma unroll
    for (int nt = 0; nt < 4; nt++) {
        bxy[nt][0] = 0.f; bxy[nt][1] = 0.f;
        if (half == 0) {
            float2 bb = __ldg((const float2*)(b1 + (wn * 32 + nt * 8 + cc * 2)));
            bxy[nt][0] = bb.x; bxy[nt][1] = bb.y;
        }
    }

    float4 v[8];
    int mt = blockIdx.x;
    if (mt < n_tiles) {
        int m0 = mt * 64;
        #pragma unroll
        for (int i = 0; i < 8; i++) {
            int idx = tid + i * 256;
            int r = idx >> 5, c4 = idx & 31;
            v[i] = make_float4(0.f, 0.f, 0.f, 0.f);
            if (m0 + r < n_nodes)
                v[i] = *(const float4*)(z + (size_t)(m0 + r) * H + c4 * 4);
        }
    }

    while (mt < n_tiles) {
        const int m0 = mt * 64;

        // ---- cvt + store current tile to As ----
        #pragma unroll
        for (int i = 0; i < 8; i++) {
            int idx = tid + i * 256;
            int r = idx >> 5, c4 = idx & 31;
            float4 t = v[i];
            t.x = to_tf32(t.x); t.y = to_tf32(t.y);
            t.z = to_tf32(t.z); t.w = to_tf32(t.w);
            *(float4*)(As + r * ASF + c4 * 4) = t;
        }
        __syncthreads();

        // ---- prefetch next tile into registers (drains during MMA) ----
        const int mt_next = mt + gridDim.x;
        if (mt_next < n_tiles) {
            int m0n = mt_next * 64;
            #pragma unroll
            for (int i = 0; i < 8; i++) {
                int idx = tid + i * 256;
                int r = idx >> 5, c4 = idx & 31;
                float4 t = make_float4(0.f, 0.f, 0.f, 0.f);
                if (m0n + r < n_nodes)
                    t = *(const float4*)(z + (size_t)(m0n + r) * H + c4 * 4);
                v[i] = t;
            }
        }

        // ---- MMA with ldmatrix fragment loads ----
        float acc[2][4][4];
        #pragma unroll
        for (int a = 0; a < 2; a++)
            #pragma unroll
            for (int b = 0; b < 4; b++)
                #pragma unroll
                for (int c = 0; c < 4; c++) acc[a][b][c] = 0.f;

        #pragma unroll
        for (int ks = 0; ks < 16; ks++) {
            const uint32_t kofs = ks * 32;
            uint32_t a[2][4], b[2][4];
            ldsm_x4(a[0], aAddr[0] + kofs);
            ldsm_x4(a[1], aAddr[1] + kofs);
            ldsm_x4(b[0], bAddr[0] + kofs);
            ldsm_x4(b[1], bAddr[1] + kofs);
            #pragma unroll
            for (int t = 0; t < 2; t++) {
                #pragma unroll
                for (int mtile = 0; mtile < 2; mtile++) {
                    mma_tf32(acc[mtile][2 * t + 0], a[mtile], b[t][0], b[t][1]);
                    mma_tf32(acc[mtile][2 * t + 1], a[mtile], b[t][2], b[t][3]);
                }
            }
        }
        __syncthreads();   // all warps done reading As before staging overwrites it

        // ---- stage epilogue to SMEM (conflict-free), b1 fused ----
        #pragma unroll
        for (int mtile = 0; mtile < 2; mtile++) {
            #pragma unroll
            for (int nt = 0; nt < 4; nt++) {
                int nloc = wn * 32 + nt * 8 + cc * 2;
                int row0 = wm * 32 + mtile * 16 + gr;   // local row
                __half2 o0 = __floats2half2_rn(acc[mtile][nt][0] + bxy[nt][0],
                                               acc[mtile][nt][1] + bxy[nt][1]);
                *(__half2*)(stg + row0 * 264 + nloc) = o0;
                __half2 o1 = __floats2half2_rn(acc[mtile][nt][2] + bxy[nt][0],
                                               acc[mtile][nt][3] + bxy[nt][1]);
                *(__half2*)(stg + (row0 + 8) * 264 + nloc) = o1;
            }
        }
        __syncthreads();

        // ---- coalesced copy-out: 64 rows x 128 halves = 1024 uint4 ----
        #pragma unroll
        for (int i = 0; i < 4; i++) {
            int idx = tid + i * 256;                // 0..1023
            int r = idx >> 4;                       // row 0..63
            int q = idx & 15;                       // uint4 slot (8 halves each)
            int m = m0 + r;
            if (m < n_nodes)
                *(uint4*)(g_ABh + (size_t)m * 256 + (size_t)half * 128 + q * 8)
                    = *(const uint4*)(stg + r * 264 + q * 8);
        }
        __syncthreads();   // staging/As free before next tile's overwrite
        mt = mt_next;
    }
}

#define SMEM_GEMM ((64 + 128) * ASF * 4)   // 101376 bytes

// ---------------- Edge pass: 8 edges/warp, per-warp dtype detect, butterfly reduce ----------------
__device__ __forceinline__ float merge2(float a, float b, int sel, int delta) {
    float u = sel ? b : a;
    float w = sel ? a : b;
    return u + __shfl_xor_sync(0xffffffffu, w, delta);
}

__global__ __launch_bounds__(256) void edge_kernel(
    const void* __restrict__ eli_raw,
    const float* __restrict__ W2,
    const float* __restrict__ b2,
    float* __restrict__ out,
    int E, int n_nodes)
{
    __shared__ float w2s[128];
    const int tid = threadIdx.x;
    if (tid < 128) w2s[tid] = W2[tid];
    __syncthreads();

    const int lane = tid & 31;
    const int warp = tid >> 5;
    const int e0 = (blockIdx.x * 8 + warp) * 8;
    if (e0 >= E) return;

    // per-warp dtype detection: 32 int64 words in-range <=> data is int64.
    // int32 data packs 2 indices/word -> hi!=0 with prob 1-1e-5 per word;
    // false-int64 prob ~ (1e-5)^32 ~ 0.
    int is64;
    {
        int e = e0 + lane; if (e >= E) e = E - 1;
        long long w = ((const long long*)eli_raw)[e];   // word index e < E: in-bounds either way
        unsigned ok = __ballot_sync(0xffffffffu, w >= 0 && w < NMAX);
        is64 = (ok == 0xffffffffu);
    }

    // lanes 0..7 load r for edges e0..e0+7; lanes 8..15 load c
    int vidx = 0;
    if (lane < 16) {
        int e = e0 + (lane & 7);
        if (e >= E) e = E - 1;
        size_t off = (lane >= 8) ? ((size_t)E + e) : (size_t)e;
        if (is64) vidx = (int)((const long long*)eli_raw)[off];
        else      vidx = ((const int*)eli_raw)[off];
        vidx = min(max(vidx, 0), n_nodes - 1);
    }

    uint2 av[8], bv[8];
    #pragma unroll
    for (int i = 0; i < 8; i++) {
        int r = __shfl_sync(0xffffffffu, vidx, i);
        int c = __shfl_sync(0xffffffffu, vidx, 8 + i);
        av[i] = *(const uint2*)(g_ABh + (size_t)r * 256 + lane * 4);
        bv[i] = *(const uint2*)(g_ABh + (size_t)c * 256 + 128 + lane * 4);
    }

    const float4 wv = *(const float4*)(w2s + lane * 4);
    const __half2 z2 = __float2half2_rn(0.f);

    float s[8];
    #pragma unroll
    for (int i = 0; i < 8; i++) {
        __half2 t0 = __hmax2(__hadd2(*(__half2*)&av[i].x, *(__half2*)&bv[i].x), z2);
        __half2 t1 = __hmax2(__hadd2(*(__half2*)&av[i].y, *(__half2*)&bv[i].y), z2);
        float2 f0 = __half22float2(t0);
        float2 f1 = __half22float2(t1);
        s[i] = fmaf(f0.x, wv.x, fmaf(f0.y, wv.y, fmaf(f1.x, wv.z, f1.y * wv.w)));
    }

    const int b0s = lane & 1, b1s = lane & 2, b2s = lane & 4;
    float t0 = merge2(s[0], s[1], b0s, 1);
    float t1 = merge2(s[2], s[3], b0s, 1);
    float t2 = merge2(s[4], s[5], b0s, 1);
    float t3 = merge2(s[6], s[7], b0s, 1);
    float u0 = merge2(t0, t1, b1s, 2);
    float u1 = merge2(t2, t3, b1s, 2);
    float p  = merge2(u0, u1, b2s, 4);
    p += __shfl_xor_sync(0xffffffffu, p, 8);
    p += __shfl_xor_sync(0xffffffffu, p, 16);

    if (lane < 8 && e0 + lane < E)
        out[e0 + lane] = p + __ldg(b2);
}

extern "C" void kernel_launch(void* const* d_in, const int* in_sizes, int n_in,
                              void* d_out, int out_size)
{
    const float* z   = (const float*)d_in[0];
    const void*  eli = d_in[1];
    const float* W1  = (const float*)d_in[2];
    const float* b1  = (const float*)d_in[3];
    const float* W2  = (const float*)d_in[4];
    const float* b2  = (const float*)d_in[5];
    float*       out = (float*)d_out;

    const int n_nodes = in_sizes[0] / H;
    const int E = out_size;

    prep_kernel<<<32, 1024>>>(W1);

    cudaFuncSetAttribute(node_gemm_tf32, cudaFuncAttributeMaxDynamicSharedMemorySize,
                         SMEM_GEMM);
    dim3 g1(148, 2);
    node_gemm_tf32<<<g1, 256, SMEM_GEMM>>>(z, b1, n_nodes);

    int blocks = (E + 63) / 64;
    edge_kernel<<<blocks, 256>>>(eli, W2, b2, out, E, n_nodes);
}

// round 17
// speedup vs baseline: 1.0071x; 1.0071x over previous
#include <cuda_runtime.h>
#include <cuda_fp16.h>
#include <cstdint>

#define H 128
#define NMAX 100000

// Scratch: per-node A = z@W1_top + b1 (cols 0..127), B = z@W1_bot (cols 128..255), fp16
__device__ __align__(16) __half g_ABh[(size_t)NMAX * 256];
// Pre-transposed, tf32-rounded Wcat^T: layout [n][k], n in [0,256), k in [0,128)
__device__ __align__(16) float g_Wt[256 * 128];

__device__ __forceinline__ float to_tf32(float x) {
    float r; asm("cvt.rna.tf32.f32 %0, %1;" : "=f"(r) : "f"(x)); return r;
}

// ---------------- prep: build W^T (tf32-rounded, transposed) ----------------
__global__ void prep_kernel(const float* __restrict__ W1) {
    int idx = blockIdx.x * blockDim.x + threadIdx.x;   // 0..32767
    int n = idx & 255;
    int k = idx >> 8;
    float v = (n < 128) ? W1[(size_t)k * 128 + n]
                        : W1[(size_t)(k + 128) * 128 + (n - 128)];
    g_Wt[(size_t)n * 128 + k] = to_tf32(v);
}

// ---------------- persistent tf32 GEMM: ldmatrix + register prefetch + staged epilogue ----------------
#define ASF 132   // fp32 words per SMEM row (132 mod 32 = 4 -> conflict-free ldmatrix)

__device__ __forceinline__ void mma_tf32(float* d, const uint32_t* a,
                                         uint32_t b0, uint32_t b1) {
    asm volatile(
        "mma.sync.aligned.m16n8k8.row.col.f32.tf32.tf32.f32 "
        "{%0,%1,%2,%3}, {%4,%5,%6,%7}, {%8,%9}, {%0,%1,%2,%3};"
        : "+f"(d[0]), "+f"(d[1]), "+f"(d[2]), "+f"(d[3])
        : "r"(a[0]), "r"(a[1]), "r"(a[2]), "r"(a[3]), "r"(b0), "r"(b1));
}

__device__ __forceinline__ uint32_t smem_u32(const void* p) {
    uint32_t a;
    asm("{ .reg .u64 t; cvta.to.shared.u64 t, %1; cvt.u32.u64 %0, t; }" : "=r"(a) : "l"(p));
    return a;
}

__device__ __forceinline__ void ldsm_x4(uint32_t* r, uint32_t saddr) {
    asm volatile("ldmatrix.sync.aligned.m8n8.x4.shared.b16 {%0,%1,%2,%3}, [%4];"
                 : "=r"(r[0]), "=r"(r[1]), "=r"(r[2]), "=r"(r[3]) : "r"(saddr));
}

__device__ __forceinline__ void cp_async16(void* smem_dst, const void* gsrc) {
    uint32_t a = smem_u32(smem_dst);
    asm volatile("cp.async.cg.shared.global [%0], [%1], 16;" :: "r"(a), "l"(gsrc) : "memory");
}

__global__ __launch_bounds__(256, 2) void node_gemm_tf32(
    const float* __restrict__ z,
    const float* __restrict__ b1,
    int n_nodes)
{
    extern __shared__ __align__(16) float smem[];
    float* As = smem;             // [64][ASF] fp32 z-tile; reused as fp16 staging [64][264]
    float* Bs = smem + 64 * ASF;  // [128 n][ASF k]
    __half* stg = (__half*)As;    // staging: 64 rows x 264 halves (132 words) = same footprint

    const int tid = threadIdx.x;
    const int wid = tid >> 5;
    const int lane = tid & 31;
    const int half = blockIdx.y;
    const int n_tiles = (n_nodes + 63) >> 6;

    // ---- async copy of pre-rounded W^T half [128 x 128] (ONCE per CTA) ----
    {
        const float* src = g_Wt + (size_t)half * 128 * 128;
        #pragma unroll
        for (int i = 0; i < 16; i++) {
            int idx = tid + i * 256;
            int r = idx >> 5;
            int q = idx & 31;
            cp_async16(Bs + r * ASF + q * 4, src + (size_t)r * 128 + q * 4);
        }
        asm volatile("cp.async.commit_group;" ::: "memory");
        asm volatile("cp.async.wait_group 0;" ::: "memory");
    }

    const int wm = wid & 1;
    const int wn = wid >> 1;
    const int gr = lane >> 2;
    const int cc = lane & 3;

    // ---- precompute ldmatrix lane addresses ----
    uint32_t aAddr[2], bAddr[2];
    {
        int lrow = (lane & 7) + 8 * ((lane >> 3) & 1);
        int lword = 4 * ((lane >> 4) & 1);
        #pragma unroll
        for (int t = 0; t < 2; t++)
            aAddr[t] = smem_u32(As + (wm * 32 + t * 16 + lrow) * ASF + lword);
        int brow = (lane & 7) + 8 * ((lane >> 4) & 1);
        int bword = 4 * ((lane >> 3) & 1);
        #pragma unroll
        for (int t = 0; t < 2; t++)
            bAddr[t] = smem_u32(Bs + (wn * 32 + t * 16 + brow) * ASF + bword);
    }

    // b1 values for this thread's columns (tile-invariant)
    float bxy[4][2];
    #pragma unroll
    for (int nt = 0; nt < 4; nt++) {
        bxy[nt][0] = 0.f; bxy[nt][1] = 0.f;
        if (half == 0) {
            float2 bb = __ldg((const float2*)(b1 + (wn * 32 + nt * 8 + cc * 2)));
            bxy[nt][0] = bb.x; bxy[nt][1] = bb.y;
        }
    }

    float4 v[8];
    int mt = blockIdx.x;
    if (mt < n_tiles) {
        int m0 = mt * 64;
        #pragma unroll
        for (int i = 0; i < 8; i++) {
            int idx = tid + i * 256;
            int r = idx >> 5, c4 = idx & 31;
            v[i] = make_float4(0.f, 0.f, 0.f, 0.f);
            if (m0 + r < n_nodes)
                v[i] = *(const float4*)(z + (size_t)(m0 + r) * H + c4 * 4);
        }
    }

    while (mt < n_tiles) {
        const int m0 = mt * 64;

        // ---- cvt + store current tile to As ----
        #pragma unroll
        for (int i = 0; i < 8; i++) {
            int idx = tid + i * 256;
            int r = idx >> 5, c4 = idx & 31;
            float4 t = v[i];
            t.x = to_tf32(t.x); t.y = to_tf32(t.y);
            t.z = to_tf32(t.z); t.w = to_tf32(t.w);
            *(float4*)(As + r * ASF + c4 * 4) = t;
        }
        __syncthreads();

        // ---- prefetch next tile into registers (drains during MMA) ----
        const int mt_next = mt + gridDim.x;
        if (mt_next < n_tiles) {
            int m0n = mt_next * 64;
            #pragma unroll
            for (int i = 0; i < 8; i++) {
                int idx = tid + i * 256;
                int r = idx >> 5, c4 = idx & 31;
                float4 t = make_float4(0.f, 0.f, 0.f, 0.f);
                if (m0n + r < n_nodes)
                    t = *(const float4*)(z + (size_t)(m0n + r) * H + c4 * 4);
                v[i] = t;
            }
        }

        // ---- MMA with ldmatrix fragment loads ----
        float acc[2][4][4];
        #pragma unroll
        for (int a = 0; a < 2; a++)
            #pragma unroll
            for (int b = 0; b < 4; b++)
                #pragma unroll
                for (int c = 0; c < 4; c++) acc[a][b][c] = 0.f;

        #pragma unroll
        for (int ks = 0; ks < 16; ks++) {
            const uint32_t kofs = ks * 32;
            uint32_t a[2][4], b[2][4];
            ldsm_x4(a[0], aAddr[0] + kofs);
            ldsm_x4(a[1], aAddr[1] + kofs);
            ldsm_x4(b[0], bAddr[0] + kofs);
            ldsm_x4(b[1], bAddr[1] + kofs);
            #pragma unroll
            for (int t = 0; t < 2; t++) {
                #pragma unroll
                for (int mtile = 0; mtile < 2; mtile++) {
                    mma_tf32(acc[mtile][2 * t + 0], a[mtile], b[t][0], b[t][1]);
                    mma_tf32(acc[mtile][2 * t + 1], a[mtile], b[t][2], b[t][3]);
                }
            }
        }
        __syncthreads();   // all warps done reading As before staging overwrites it

        // ---- stage epilogue to SMEM (conflict-free), b1 fused ----
        #pragma unroll
        for (int mtile = 0; mtile < 2; mtile++) {
            #pragma unroll
            for (int nt = 0; nt < 4; nt++) {
                int nloc = wn * 32 + nt * 8 + cc * 2;
                int row0 = wm * 32 + mtile * 16 + gr;   // local row
                __half2 o0 = __floats2half2_rn(acc[mtile][nt][0] + bxy[nt][0],
                                               acc[mtile][nt][1] + bxy[nt][1]);
                *(__half2*)(stg + row0 * 264 + nloc) = o0;
                __half2 o1 = __floats2half2_rn(acc[mtile][nt][2] + bxy[nt][0],
                                               acc[mtile][nt][3] + bxy[nt][1]);
                *(__half2*)(stg + (row0 + 8) * 264 + nloc) = o1;
            }
        }
        __syncthreads();

        // ---- coalesced copy-out: 64 rows x 128 halves = 1024 uint4 ----
        #pragma unroll
        for (int i = 0; i < 4; i++) {
            int idx = tid + i * 256;                // 0..1023
            int r = idx >> 4;                       // row 0..63
            int q = idx & 15;                       // uint4 slot (8 halves each)
            int m = m0 + r;
            if (m < n_nodes)
                *(uint4*)(g_ABh + (size_t)m * 256 + (size_t)half * 128 + q * 8)
                    = *(const uint4*)(stg + r * 264 + q * 8);
        }
        __syncthreads();   // staging/As free before next tile's overwrite
        mt = mt_next;
    }
}

#define SMEM_GEMM ((64 + 128) * ASF * 4)   // 101376 bytes

// ---------------- Edge pass: 8 edges/warp, per-warp dtype detect, butterfly reduce ----------------
__device__ __forceinline__ float merge2(float a, float b, int sel, int delta) {
    float u = sel ? b : a;
    float w = sel ? a : b;
    return u + __shfl_xor_sync(0xffffffffu, w, delta);
}

__global__ __launch_bounds__(256) void edge_kernel(
    const void* __restrict__ eli_raw,
    const float* __restrict__ W2,
    const float* __restrict__ b2,
    float* __restrict__ out,
    int E, int n_nodes)
{
    __shared__ float w2s[128];
    const int tid = threadIdx.x;
    if (tid < 128) w2s[tid] = W2[tid];
    __syncthreads();

    const int lane = tid & 31;
    const int warp = tid >> 5;
    const int e0 = (blockIdx.x * 8 + warp) * 8;
    if (e0 >= E) return;

    // per-warp dtype detection: 32 int64 words in-range <=> data is int64.
    // int32 data packs 2 indices/word -> hi!=0 with prob 1-1e-5 per word;
    // false-int64 prob ~ (1e-5)^32 ~ 0.
    int is64;
    {
        int e = e0 + lane; if (e >= E) e = E - 1;
        long long w = ((const long long*)eli_raw)[e];   // word index e < E: in-bounds either way
        unsigned ok = __ballot_sync(0xffffffffu, w >= 0 && w < NMAX);
        is64 = (ok == 0xffffffffu);
    }

    // lanes 0..7 load r for edges e0..e0+7; lanes 8..15 load c
    int vidx = 0;
    if (lane < 16) {
        int e = e0 + (lane & 7);
        if (e >= E) e = E - 1;
        size_t off = (lane >= 8) ? ((size_t)E + e) : (size_t)e;
        if (is64) vidx = (int)((const long long*)eli_raw)[off];
        else      vidx = ((const int*)eli_raw)[off];
        vidx = min(max(vidx, 0), n_nodes - 1);
    }

    uint2 av[8], bv[8];
    #pragma unroll
    for (int i = 0; i < 8; i++) {
        int r = __shfl_sync(0xffffffffu, vidx, i);
        int c = __shfl_sync(0xffffffffu, vidx, 8 + i);
        av[i] = *(const uint2*)(g_ABh + (size_t)r * 256 + lane * 4);
        bv[i] = *(const uint2*)(g_ABh + (size_t)c * 256 + 128 + lane * 4);
    }

    const float4 wv = *(const float4*)(w2s + lane * 4);
    const __half2 z2 = __float2half2_rn(0.f);

    float s[8];
    #pragma unroll
    for (int i = 0; i < 8; i++) {
        __half2 t0 = __hmax2(__hadd2(*(__half2*)&av[i].x, *(__half2*)&bv[i].x), z2);
        __half2 t1 = __hmax2(__hadd2(*(__half2*)&av[i].y, *(__half2*)&bv[i].y), z2);
        float2 f0 = __half22float2(t0);
        float2 f1 = __half22float2(t1);
        s[i] = fmaf(f0.x, wv.x, fmaf(f0.y, wv.y, fmaf(f1.x, wv.z, f1.y * wv.w)));
    }

    const int b0s = lane & 1, b1s = lane & 2, b2s = lane & 4;
    float t0 = merge2(s[0], s[1], b0s, 1);
    float t1 = merge2(s[2], s[3], b0s, 1);
    float t2 = merge2(s[4], s[5], b0s, 1);
    float t3 = merge2(s[6], s[7], b0s, 1);
    float u0 = merge2(t0, t1, b1s, 2);
    float u1 = merge2(t2, t3, b1s, 2);
    float p  = merge2(u0, u1, b2s, 4);
    p += __shfl_xor_sync(0xffffffffu, p, 8);
    p += __shfl_xor_sync(0xffffffffu, p, 16);

    if (lane < 8 && e0 + lane < E)
        out[e0 + lane] = p + __ldg(b2);
}

extern "C" void kernel_launch(void* const* d_in, const int* in_sizes, int n_in,
                              void* d_out, int out_size)
{
    const float* z   = (const float*)d_in[0];
    const void*  eli = d_in[1];
    const float* W1  = (const float*)d_in[2];
    const float* b1  = (const float*)d_in[3];
    const float* W2  = (const float*)d_in[4];
    const float* b2  = (const float*)d_in[5];
    float*       out = (float*)d_out;

    const int n_nodes = in_sizes[0] / H;
    const int E = out_size;

    prep_kernel<<<32, 1024>>>(W1);

    cudaFuncSetAttribute(node_gemm_tf32, cudaFuncAttributeMaxDynamicSharedMemorySize,
                         SMEM_GEMM);
    dim3 g1(148, 2);
    node_gemm_tf32<<<g1, 256, SMEM_GEMM>>>(z, b1, n_nodes);

    int blocks = (E + 63) / 64;
    edge_kernel<<<blocks, 256>>>(eli, W2, b2, out, E, n_nodes);
}